// round 11
// baseline (speedup 1.0000x reference)
#include <cuda_runtime.h>
#include <cuda_fp16.h>
#include <cstdint>

// Problem constants
#define BQ 16
#define NQ 4096
#define DQ 256
#define KQ 4096
#define MQ (BQ*NQ)   // 65536 tokens

#define DECAYF 0.99f
#define ONEMDECAYF 0.01f
#define EPSF 1e-5f

// fp16 2-way split, shared-fragment 3-product scheme
#define ROWH 512             // halfs per row
#define ROWB 1024            // bytes per row
#define SLDA 80              // smem sub-tile row stride (bytes), conflict-free
#define SUBT (128*SLDA)      // 10240 bytes per 128x32half sub-tile
#define STAGEB (4*SUBT)      // Ah0|Ah1|Bg0|Bg1 = 40960
#define NCHUNK 8             // k32 chunks covering D=256
#define NQUARTER 1024        // codes per CTA (N-split x4)
#define NTILES (NQUARTER/128) // 8
#define TOTQ (NTILES*NCHUNK) // 64
#define SMEM_DIST (2*STAGEB + 1024)   // 2 stages + sbest = 82944

// ---------------- device scratch (no allocations allowed) ----------------
__device__ __align__(16) __half g_zbig[(size_t)MQ * ROWH];   // [M][h0|h1] (z*16)
__device__ __align__(16) __half g_ebig[(size_t)KQ * ROWH];   // [K][g0|g1] (e*16)
__device__ unsigned long long g_best[MQ];   // (ordered score <<32)|index
__device__ float  g_enorm[KQ];
__device__ float  g_cs[KQ];
__device__ float  g_es[KQ*DQ];
__device__ int    g_cnt[MQ/128];            // per-row-block completion counters
__device__ double g_loss;
__device__ float  g_tot;

// ---------------- helpers ----------------
__device__ __forceinline__ uint32_t s2u(const void* p) {
    uint32_t a;
    asm("{ .reg .u64 t; cvta.to.shared.u64 t, %1; cvt.u32.u64 %0, t; }"
        : "=r"(a) : "l"(p));
    return a;
}
__device__ __forceinline__ unsigned int fkey(float f) {
    unsigned int b = __float_as_uint(f);
    return b ^ ((b & 0x80000000u) ? 0xFFFFFFFFu : 0x80000000u);
}
__device__ __forceinline__ unsigned long long umin64(unsigned long long a,
                                                     unsigned long long b) {
    return a < b ? a : b;
}
__device__ __forceinline__ void cp16(uint32_t dst, const void* src) {
    asm volatile("cp.async.cg.shared.global [%0], [%1], 16;" :: "r"(dst), "l"(src));
}
#define CP_COMMIT() asm volatile("cp.async.commit_group;" ::: "memory")

__device__ __forceinline__ void ldsm4(uint32_t& r0, uint32_t& r1, uint32_t& r2,
                                      uint32_t& r3, uint32_t a) {
    asm volatile("ldmatrix.sync.aligned.m8n8.x4.shared.b16 {%0,%1,%2,%3}, [%4];"
                 : "=r"(r0), "=r"(r1), "=r"(r2), "=r"(r3) : "r"(a));
}
__device__ __forceinline__ void mma16816(float* c, const uint32_t* a,
                                         uint32_t b0, uint32_t b1) {
    asm volatile(
        "mma.sync.aligned.m16n8k16.row.col.f32.f16.f16.f32 "
        "{%0,%1,%2,%3}, {%4,%5,%6,%7}, {%8,%9}, {%0,%1,%2,%3};"
        : "+f"(c[0]), "+f"(c[1]), "+f"(c[2]), "+f"(c[3])
        : "r"(a[0]), "r"(a[1]), "r"(a[2]), "r"(a[3]), "r"(b0), "r"(b1));
}
__device__ __forceinline__ void red2(float* addr, float a, float b) {
    asm volatile("red.global.add.v2.f32 [%0], {%1, %2};"
                 :: "l"(addr), "f"(a), "f"(b) : "memory");
}
__device__ __forceinline__ unsigned long long ldcg64(const unsigned long long* p) {
    unsigned long long v;
    asm volatile("ld.global.cg.u64 %0, [%1];" : "=l"(v) : "l"(p));
    return v;
}

// ---------------- splits (scale x16, fp16 2-way Dekker) + g_best init ----------------
#define ZBLKS (MQ*DQ/2/256)   // 32768
__global__ void split_z_kernel(const float* __restrict__ z) {
    int b = blockIdx.x;
    if (b >= ZBLKS) {
        int i = (b - ZBLKS) * 256 + threadIdx.x;   // 256 blocks x 256 = 65536
        g_best[i] = 0xFFFFFFFFFFFFFFFFull;
        return;
    }
    int i = b * 256 + threadIdx.x;
    int idx = i * 2;
    int row = idx >> 8;
    int d = idx & 255;
    float2 v = *reinterpret_cast<const float2*>(z + idx);
    float sx = v.x * 16.0f, sy = v.y * 16.0f;
    __half hx0 = __float2half(sx), hy0 = __float2half(sy);
    __half hx1 = __float2half(sx - __half2float(hx0));
    __half hy1 = __float2half(sy - __half2float(hy0));
    __half* base = g_zbig + (size_t)row * ROWH + d;
    __half2 p0; p0.x = hx0; p0.y = hy0;
    __half2 p1; p1.x = hx1; p1.y = hy1;
    *reinterpret_cast<__half2*>(base)       = p0;   // h0
    *reinterpret_cast<__half2*>(base + 256) = p1;   // h1
}

#define EBLKS (KQ*DQ/2/256)   // 2048
__global__ void split_e_kernel(const float* __restrict__ e) {
    int b = blockIdx.x;
    if (b >= EBLKS) {
        int tb = b - EBLKS;
        if (tb < 1024) {                      // zero g_es (1M floats via float4)
            int i = tb * 256 + threadIdx.x;
            reinterpret_cast<float4*>(g_es)[i] = make_float4(0.f, 0.f, 0.f, 0.f);
        } else if (tb < 1040) {               // zero g_cs (4096 floats)
            g_cs[(tb - 1024) * 256 + threadIdx.x] = 0.f;
        } else {                              // counters + scalars
            int t = threadIdx.x;
            g_cnt[t] = 0; g_cnt[t + 256] = 0;
            if (t == 0) { g_loss = 0.0; g_tot = 0.f; }
        }
        return;
    }
    int i = b * 256 + threadIdx.x;
    int idx = i * 2;
    int row = idx >> 8;
    int d = idx & 255;
    float2 v = *reinterpret_cast<const float2*>(e + idx);
    float sx = v.x * 16.0f, sy = v.y * 16.0f;
    __half gx0 = __float2half(sx), gy0 = __float2half(sy);
    __half gx1 = __float2half(sx - __half2float(gx0));
    __half gy1 = __float2half(sy - __half2float(gy0));
    __half* base = g_ebig + (size_t)row * ROWH + d;
    __half2 p0; p0.x = gx0; p0.y = gy0;
    __half2 p1; p1.x = gx1; p1.y = gy1;
    *reinterpret_cast<__half2*>(base)       = p0;   // g0
    *reinterpret_cast<__half2*>(base + 256) = p1;   // g1
}

// ---------------- ||e_k||^2 (unscaled fp32) ----------------
__global__ void enorm_kernel(const float* __restrict__ embed) {
    int k = blockIdx.x;
    int t = threadIdx.x;                 // 64 threads x 4 floats
    const float4* row = reinterpret_cast<const float4*>(embed + (size_t)k * DQ);
    float4 v = row[t];
    float s = v.x*v.x + v.y*v.y + v.z*v.z + v.w*v.w;
    #pragma unroll
    for (int off = 16; off; off >>= 1) s += __shfl_down_sync(0xffffffffu, s, off);
    __shared__ float sh[2];
    if ((t & 31) == 0) sh[t >> 5] = s;
    __syncthreads();
    if (t == 0) g_enorm[k] = sh[0] + sh[1];
}

// ---------------- chunk loader: Ah0|Ah1|Bg0|Bg1 sub-tiles ----------------
__device__ __forceinline__ void issue_chunk(uint32_t stage, int mBase, int nBase, int kc) {
    const char* zB = (const char*)g_zbig;
    const char* eB = (const char*)g_ebig;
    const int kb = kc * 64;
    #pragma unroll
    for (int j = 0; j < 8; j++) {
        int id = threadIdx.x + j * 256;     // 0..2047
        int sub = id >> 9;
        int r = (id >> 2) & 127;
        int c = (id & 3) * 16;
        const char* src = (sub < 2)
            ? zB + (size_t)(mBase + r) * ROWB + sub * 512 + kb + c
            : eB + (size_t)(nBase + r) * ROWB + (sub - 2) * 512 + kb + c;
        cp16(stage + sub * SUBT + r * SLDA + c, src);
    }
    CP_COMMIT();
}

// ---------------- fused HMMA distance GEMM + argmin + gather ----------------
__global__ __launch_bounds__(256, 2)
void dist_hmma_kernel(const float* __restrict__ z, const float* __restrict__ embed,
                      float* __restrict__ out_zq, float* __restrict__ out_idx) {
    extern __shared__ char smem[];
    uint32_t sb = s2u(smem);
    const int tid = threadIdx.x;
    const int lane = tid & 31;
    const int wid = tid >> 5;
    const int wm = wid & 3;
    const int wn = wid >> 2;
    const int mb = (int)(blockIdx.x >> 2);
    const int mBase = mb * 128;
    const int nQ0   = (int)(blockIdx.x & 3) * NQUARTER;

    unsigned long long* sbest = (unsigned long long*)(smem + 2 * STAGEB);

    const uint32_t aLane = (uint32_t)((wm * 32 + (lane & 15)) * SLDA + ((lane & 16) ? 16 : 0));
    const uint32_t bLane = (uint32_t)((wn * 64 + ((lane >> 4) & 1) * 8 + (lane & 7)) * SLDA
                                      + ((lane & 8) ? 16 : 0));

    unsigned long long best4[4];
    #pragma unroll
    for (int s = 0; s < 4; s++) best4[s] = 0xFFFFFFFFFFFFFFFFull;

    float c[2][8][4];

    // prologue
    issue_chunk(sb, mBase, nQ0, 0);

    for (int qc = 0; qc < TOTQ; qc++) {
        const int nt = qc >> 3;
        const int kc = qc & 7;
        if (qc < TOTQ - 1) {
            const int qn = qc + 1;
            issue_chunk(sb + (qn & 1) * STAGEB, mBase, nQ0 + (qn >> 3) * 128, qn & 7);
            asm volatile("cp.async.wait_group 1;" ::: "memory");
        } else {
            asm volatile("cp.async.wait_group 0;" ::: "memory");
        }
        __syncthreads();

        if (kc == 0) {
            #pragma unroll
            for (int mf = 0; mf < 2; mf++)
                #pragma unroll
                for (int nf = 0; nf < 8; nf++)
                    #pragma unroll
                    for (int r = 0; r < 4; r++) c[mf][nf][r] = 0.f;
        }

        const uint32_t sbuf = sb + (qc & 1) * STAGEB;
        #pragma unroll
        for (int k16 = 0; k16 < 2; k16++) {
            const uint32_t kb = k16 * 32;
            uint32_t a0[2][4], a1[2][4];
            #pragma unroll
            for (int mf = 0; mf < 2; mf++) {
                ldsm4(a0[mf][0], a0[mf][1], a0[mf][2], a0[mf][3],
                      sbuf + aLane + mf * (16 * SLDA) + kb);
                ldsm4(a1[mf][0], a1[mf][1], a1[mf][2], a1[mf][3],
                      sbuf + SUBT + aLane + mf * (16 * SLDA) + kb);
            }
            #pragma unroll
            for (int np = 0; np < 2; np++) {
                const int n0 = 2 * np;
                uint32_t P[2][4], Q[2][4];
                #pragma unroll
                for (int j = 0; j < 2; j++) {
                    ldsm4(P[j][0], P[j][1], P[j][2], P[j][3],
                          sbuf + 2 * SUBT + bLane + (n0 + j) * (16 * SLDA) + kb);
                    ldsm4(Q[j][0], Q[j][1], Q[j][2], Q[j][3],
                          sbuf + 3 * SUBT + bLane + (n0 + j) * (16 * SLDA) + kb);
                }
                #pragma unroll
                for (int j = 0; j < 2; j++)
                    #pragma unroll
                    for (int mf = 0; mf < 2; mf++) {
                        mma16816(c[mf][2*(n0+j)],   a0[mf], P[j][0], P[j][1]);
                        mma16816(c[mf][2*(n0+j)+1], a0[mf], P[j][2], P[j][3]);
                    }
                #pragma unroll
                for (int j = 0; j < 2; j++)
                    #pragma unroll
                    for (int mf = 0; mf < 2; mf++) {
                        mma16816(c[mf][2*(n0+j)],   a1[mf], P[j][0], P[j][1]);
                        mma16816(c[mf][2*(n0+j)+1], a1[mf], P[j][2], P[j][3]);
                    }
                #pragma unroll
                for (int j = 0; j < 2; j++)
                    #pragma unroll
                    for (int mf = 0; mf < 2; mf++) {
                        mma16816(c[mf][2*(n0+j)],   a0[mf], Q[j][0], Q[j][1]);
                        mma16816(c[mf][2*(n0+j)+1], a0[mf], Q[j][2], Q[j][3]);
                    }
            }
        }
        __syncthreads();

        if (kc == NCHUNK - 1) {
            const int colBase = nQ0 + nt * 128 + wn * 64 + (lane & 3) * 2;
            float En16[16];
            #pragma unroll
            for (int nf = 0; nf < 8; nf++) {
                En16[nf*2]   = __ldg(&g_enorm[colBase + nf * 8]);
                En16[nf*2+1] = __ldg(&g_enorm[colBase + nf * 8 + 1]);
            }
            #pragma unroll
            for (int mf = 0; mf < 2; mf++)
                #pragma unroll
                for (int rh = 0; rh < 2; rh++) {
                    float s[16];
                    #pragma unroll
                    for (int nf = 0; nf < 8; nf++) {
                        s[nf*2]   = En16[nf*2]   - 0.0078125f * c[mf][nf][rh*2];
                        s[nf*2+1] = En16[nf*2+1] - 0.0078125f * c[mf][nf][rh*2+1];
                    }
                    float m = s[0];
                    #pragma unroll
                    for (int i = 1; i < 16; i++) m = fminf(m, s[i]);
                    int col = colBase;
                    #pragma unroll
                    for (int i = 15; i >= 0; i--)
                        if (s[i] == m) col = colBase + (i >> 1) * 8 + (i & 1);
                    unsigned long long key =
                        ((unsigned long long)fkey(m) << 32) | (unsigned)col;
                    int slot = mf * 2 + rh;
                    best4[slot] = umin64(best4[slot], key);
                }
        }
    }

    // quad reduction, smem combine, global atomicMin
    #pragma unroll
    for (int s = 0; s < 4; s++) {
        best4[s] = umin64(best4[s], __shfl_xor_sync(0xffffffffu, best4[s], 1));
        best4[s] = umin64(best4[s], __shfl_xor_sync(0xffffffffu, best4[s], 2));
    }
    if ((lane & 3) == 0 && wn == 0) {
        #pragma unroll
        for (int s = 0; s < 4; s++) {
            int row = wm * 32 + (s >> 1) * 16 + (s & 1) * 8 + (lane >> 2);
            sbest[row] = best4[s];
        }
    }
    __syncthreads();
    if ((lane & 3) == 0 && wn == 1) {
        #pragma unroll
        for (int s = 0; s < 4; s++) {
            int row = wm * 32 + (s >> 1) * 16 + (s & 1) * 8 + (lane >> 2);
            atomicMin(&g_best[mBase + row], umin64(sbest[row], best4[s]));
        }
    }

    // ---- completion counter: last of the 4 N-quarter CTAs gathers ----
    __threadfence();
    __syncthreads();
    __shared__ int sLast;
    if (tid == 0) {
        int old = atomicAdd(&g_cnt[mb], 1);
        sLast = (old == 3) ? 1 : 0;
    }
    __syncthreads();
    if (sLast) {
        __threadfence();   // acquire side
        const int r = tid >> 1;           // 0..127
        const int half = tid & 1;         // 128 dims each
        const int row = mBase + r;
        unsigned long long best = ldcg64(&g_best[row]);
        const int idx = (int)(unsigned)(best & 0xFFFFFFFFull);
        const float* zrow  = z      + (size_t)row * DQ + half * 128;
        const float* erow  = embed  + (size_t)idx * DQ + half * 128;
        float*       zqrow = out_zq + (size_t)row * DQ + half * 128;
        float*       esrow = g_es   + (size_t)idx * DQ + half * 128;
        float lsum = 0.f;
        #pragma unroll
        for (int j = 0; j < 32; j++) {
            float4 zv = *reinterpret_cast<const float4*>(zrow + j * 4);
            float4 eq = *reinterpret_cast<const float4*>(erow + j * 4);
            *reinterpret_cast<float4*>(zqrow + j * 4) = eq;
            red2(esrow + j * 4,     zv.x, zv.y);
            red2(esrow + j * 4 + 2, zv.z, zv.w);
            float dx = eq.x - zv.x, dy = eq.y - zv.y;
            float dz = eq.z - zv.z, dw = eq.w - zv.w;
            lsum += dx*dx + dy*dy + dz*dz + dw*dw;
        }
        if (half == 0) {
            out_idx[row] = (float)idx;
            atomicAdd(&g_cs[idx], 1.0f);
        }
        #pragma unroll
        for (int off = 16; off; off >>= 1)
            lsum += __shfl_down_sync(0xffffffffu, lsum, off);
        __shared__ float shl[8];
        if (lane == 0) shl[wid] = lsum;
        __syncthreads();
        if (tid == 0) {
            float t = 0.f;
            #pragma unroll
            for (int w = 0; w < 8; w++) t += shl[w];
            atomicAdd(&g_loss, (double)t);
        }
    }
}

// ---------------- EMA cluster size + total + loss write ----------------
__global__ void ncs_kernel(const float* __restrict__ cluster_size,
                           float* __restrict__ out_ncs, float* __restrict__ out_loss) {
    int k = blockIdx.x * blockDim.x + threadIdx.x;   // 4096
    float ncs = cluster_size[k] * DECAYF + ONEMDECAYF * g_cs[k];
    out_ncs[k] = ncs;
    float s = ncs;
    #pragma unroll
    for (int off = 16; off; off >>= 1) s += __shfl_down_sync(0xffffffffu, s, off);
    __shared__ float sh[8];
    int lt = threadIdx.x;
    if ((lt & 31) == 0) sh[lt >> 5] = s;
    __syncthreads();
    if (lt == 0) {
        float tot = 0.f;
        #pragma unroll
        for (int w = 0; w < 8; w++) tot += sh[w];
        atomicAdd(&g_tot, tot);
    }
    if (k == 0) out_loss[0] = (float)(2.0 * g_loss / (double)((size_t)MQ * DQ));
}

// ---------------- EMA embed_avg + normalized embed ----------------
__global__ void final_kernel(const float* __restrict__ embed_avg,
                             const float* __restrict__ out_ncs,
                             float* __restrict__ out_new_embed,
                             float* __restrict__ out_nea) {
    int i = blockIdx.x * blockDim.x + threadIdx.x;   // K*D
    int k = i >> 8;
    float tot = g_tot;
    float ncs = out_ncs[k];
    float csn = (ncs + EPSF) / (tot + (float)KQ * EPSF) * tot;
    float nea = embed_avg[i] * DECAYF + ONEMDECAYF * g_es[i];
    out_nea[i] = nea;
    out_new_embed[i] = nea / csn;
}

// ---------------- launch ----------------
extern "C" void kernel_launch(void* const* d_in, const int* in_sizes, int n_in,
                              void* d_out, int out_size) {
    const float* z            = (const float*)d_in[0];
    const float* embed        = (const float*)d_in[1];
    const float* cluster_size = (const float*)d_in[2];
    const float* embed_avg    = (const float*)d_in[3];

    float* out          = (float*)d_out;
    float* out_zq       = out;                                   // [B,N,D]
    float* out_idx      = out + (size_t)MQ * DQ;                 // [B,N]
    float* out_loss     = out_idx + MQ;                          // [1]
    float* out_newembed = out_loss + 1;                          // [K,D]
    float* out_ncs      = out_newembed + (size_t)KQ * DQ;        // [K]
    float* out_nea      = out_ncs + KQ;                          // [K,D]

    cudaFuncSetAttribute(dist_hmma_kernel,
                         cudaFuncAttributeMaxDynamicSharedMemorySize, SMEM_DIST);

    split_z_kernel<<<ZBLKS + 256, 256>>>(z);
    split_e_kernel<<<EBLKS + 1041, 256>>>(embed);
    enorm_kernel<<<KQ, 64>>>(embed);
    dist_hmma_kernel<<<(MQ / 128) * 4, 256, SMEM_DIST>>>(z, embed, out_zq, out_idx);
    ncs_kernel<<<KQ / 256, 256>>>(cluster_size, out_ncs, out_loss);
    final_kernel<<<(KQ * DQ) / 256, 256>>>(embed_avg, out_ncs, out_newembed, out_nea);
}

// round 12
// speedup vs baseline: 1.0718x; 1.0718x over previous
#include <cuda_runtime.h>
#include <cuda_fp16.h>
#include <cstdint>

// Problem constants
#define BQ 16
#define NQ 4096
#define DQ 256
#define KQ 4096
#define MQ (BQ*NQ)   // 65536 tokens

#define DECAYF 0.99f
#define ONEMDECAYF 0.01f
#define EPSF 1e-5f

// fp16 2-way split, shared-fragment 3-product scheme
#define ROWH 512             // halfs per row
#define ROWB 1024            // bytes per row
#define SLDA 80              // smem sub-tile row stride (bytes), conflict-free
#define SUBT (128*SLDA)      // 10240 bytes per 128x32half sub-tile
#define STAGEB (4*SUBT)      // Ah0|Ah1|Bg0|Bg1 = 40960
#define NCHUNK 8             // k32 chunks covering D=256
#define NQUARTER 1024        // codes per CTA (N-split x4)
#define NTILES (NQUARTER/128) // 8
#define TOTQ (NTILES*NCHUNK) // 64
#define SMEM_DIST (2*STAGEB + 1024)   // 2 stages + sbest = 82944

// ---------------- device scratch (no allocations allowed) ----------------
__device__ __align__(16) __half g_zbig[(size_t)MQ * ROWH];   // [M][h0|h1] (z*16)
__device__ __align__(16) __half g_ebig[(size_t)KQ * ROWH];   // [K][g0|g1] (e*16)
__device__ unsigned long long g_best[MQ];   // (ordered score <<32)|index
__device__ float  g_enorm[KQ];
__device__ float  g_cs[KQ];
__device__ float  g_es[KQ*DQ];
__device__ double g_loss;
__device__ float  g_tot;

// ---------------- helpers ----------------
__device__ __forceinline__ uint32_t s2u(const void* p) {
    uint32_t a;
    asm("{ .reg .u64 t; cvta.to.shared.u64 t, %1; cvt.u32.u64 %0, t; }"
        : "=r"(a) : "l"(p));
    return a;
}
__device__ __forceinline__ unsigned int fkey(float f) {
    unsigned int b = __float_as_uint(f);
    return b ^ ((b & 0x80000000u) ? 0xFFFFFFFFu : 0x80000000u);
}
__device__ __forceinline__ unsigned long long umin64(unsigned long long a,
                                                     unsigned long long b) {
    return a < b ? a : b;
}
__device__ __forceinline__ void cp16(uint32_t dst, const void* src) {
    asm volatile("cp.async.cg.shared.global [%0], [%1], 16;" :: "r"(dst), "l"(src));
}
#define CP_COMMIT() asm volatile("cp.async.commit_group;" ::: "memory")

__device__ __forceinline__ void ldsm4(uint32_t& r0, uint32_t& r1, uint32_t& r2,
                                      uint32_t& r3, uint32_t a) {
    asm volatile("ldmatrix.sync.aligned.m8n8.x4.shared.b16 {%0,%1,%2,%3}, [%4];"
                 : "=r"(r0), "=r"(r1), "=r"(r2), "=r"(r3) : "r"(a));
}
__device__ __forceinline__ void mma16816(float* c, const uint32_t* a,
                                         uint32_t b0, uint32_t b1) {
    asm volatile(
        "mma.sync.aligned.m16n8k16.row.col.f32.f16.f16.f32 "
        "{%0,%1,%2,%3}, {%4,%5,%6,%7}, {%8,%9}, {%0,%1,%2,%3};"
        : "+f"(c[0]), "+f"(c[1]), "+f"(c[2]), "+f"(c[3])
        : "r"(a[0]), "r"(a[1]), "r"(a[2]), "r"(a[3]), "r"(b0), "r"(b1));
}
__device__ __forceinline__ void red2(float* addr, float a, float b) {
    asm volatile("red.global.add.v2.f32 [%0], {%1, %2};"
                 :: "l"(addr), "f"(a), "f"(b) : "memory");
}

// ---------------- splits (scale x16, fp16 2-way Dekker) + g_best init ----------------
#define ZBLKS (MQ*DQ/2/256)   // 32768
__global__ void split_z_kernel(const float* __restrict__ z) {
    int b = blockIdx.x;
    if (b >= ZBLKS) {
        int i = (b - ZBLKS) * 256 + threadIdx.x;   // 256 blocks x 256 = 65536
        g_best[i] = 0xFFFFFFFFFFFFFFFFull;
        return;
    }
    int i = b * 256 + threadIdx.x;
    int idx = i * 2;
    int row = idx >> 8;
    int d = idx & 255;
    float2 v = *reinterpret_cast<const float2*>(z + idx);
    float sx = v.x * 16.0f, sy = v.y * 16.0f;
    __half hx0 = __float2half(sx), hy0 = __float2half(sy);
    __half hx1 = __float2half(sx - __half2float(hx0));
    __half hy1 = __float2half(sy - __half2float(hy0));
    __half* base = g_zbig + (size_t)row * ROWH + d;
    __half2 p0; p0.x = hx0; p0.y = hy0;
    __half2 p1; p1.x = hx1; p1.y = hy1;
    *reinterpret_cast<__half2*>(base)       = p0;   // h0
    *reinterpret_cast<__half2*>(base + 256) = p1;   // h1
}

#define EBLKS (KQ*DQ/2/256)   // 2048
__global__ void split_e_kernel(const float* __restrict__ e) {
    int b = blockIdx.x;
    if (b >= EBLKS) {
        int tb = b - EBLKS;
        if (tb < 1024) {                      // zero g_es (1M floats via float4)
            int i = tb * 256 + threadIdx.x;
            reinterpret_cast<float4*>(g_es)[i] = make_float4(0.f, 0.f, 0.f, 0.f);
        } else {                              // zero g_cs + scalars
            int t = threadIdx.x;
            int k0 = (tb - 1024) * 256 + t;
            if (k0 < KQ) g_cs[k0] = 0.f;
            if (tb == 1024 && t == 0) { g_loss = 0.0; g_tot = 0.f; }
        }
        return;
    }
    int i = b * 256 + threadIdx.x;
    int idx = i * 2;
    int row = idx >> 8;
    int d = idx & 255;
    float2 v = *reinterpret_cast<const float2*>(e + idx);
    float sx = v.x * 16.0f, sy = v.y * 16.0f;
    __half gx0 = __float2half(sx), gy0 = __float2half(sy);
    __half gx1 = __float2half(sx - __half2float(gx0));
    __half gy1 = __float2half(sy - __half2float(gy0));
    __half* base = g_ebig + (size_t)row * ROWH + d;
    __half2 p0; p0.x = gx0; p0.y = gy0;
    __half2 p1; p1.x = gx1; p1.y = gy1;
    *reinterpret_cast<__half2*>(base)       = p0;   // g0
    *reinterpret_cast<__half2*>(base + 256) = p1;   // g1
}

// ---------------- ||e_k||^2 (unscaled fp32) ----------------
__global__ void enorm_kernel(const float* __restrict__ embed) {
    int k = blockIdx.x;
    int t = threadIdx.x;                 // 64 threads x 4 floats
    const float4* row = reinterpret_cast<const float4*>(embed + (size_t)k * DQ);
    float4 v = row[t];
    float s = v.x*v.x + v.y*v.y + v.z*v.z + v.w*v.w;
    #pragma unroll
    for (int off = 16; off; off >>= 1) s += __shfl_down_sync(0xffffffffu, s, off);
    __shared__ float sh[2];
    if ((t & 31) == 0) sh[t >> 5] = s;
    __syncthreads();
    if (t == 0) g_enorm[k] = sh[0] + sh[1];
}

// ---------------- chunk loader: Ah0|Ah1|Bg0|Bg1 sub-tiles ----------------
__device__ __forceinline__ void issue_chunk(uint32_t stage, int mBase, int nBase, int kc) {
    const char* zB = (const char*)g_zbig;
    const char* eB = (const char*)g_ebig;
    const int kb = kc * 64;
    #pragma unroll
    for (int j = 0; j < 8; j++) {
        int id = threadIdx.x + j * 256;     // 0..2047
        int sub = id >> 9;
        int r = (id >> 2) & 127;
        int c = (id & 3) * 16;
        const char* src = (sub < 2)
            ? zB + (size_t)(mBase + r) * ROWB + sub * 512 + kb + c
            : eB + (size_t)(nBase + r) * ROWB + (sub - 2) * 512 + kb + c;
        cp16(stage + sub * SUBT + r * SLDA + c, src);
    }
    CP_COMMIT();
}

// ---------------- fused HMMA distance GEMM + argmin ----------------
__global__ __launch_bounds__(256, 2)
void dist_hmma_kernel() {
    extern __shared__ char smem[];
    uint32_t sb = s2u(smem);
    const int tid = threadIdx.x;
    const int lane = tid & 31;
    const int wid = tid >> 5;
    const int wm = wid & 3;
    const int wn = wid >> 2;
    const int mBase = (int)(blockIdx.x >> 2) * 128;
    const int nQ0   = (int)(blockIdx.x & 3) * NQUARTER;

    unsigned long long* sbest = (unsigned long long*)(smem + 2 * STAGEB);

    const uint32_t aLane = (uint32_t)((wm * 32 + (lane & 15)) * SLDA + ((lane & 16) ? 16 : 0));
    const uint32_t bLane = (uint32_t)((wn * 64 + ((lane >> 4) & 1) * 8 + (lane & 7)) * SLDA
                                      + ((lane & 8) ? 16 : 0));

    unsigned long long best4[4];
    #pragma unroll
    for (int s = 0; s < 4; s++) best4[s] = 0xFFFFFFFFFFFFFFFFull;

    float c[2][8][4];

    // prologue
    issue_chunk(sb, mBase, nQ0, 0);

    for (int qc = 0; qc < TOTQ; qc++) {
        const int nt = qc >> 3;
        const int kc = qc & 7;
        if (qc < TOTQ - 1) {
            const int qn = qc + 1;
            issue_chunk(sb + (qn & 1) * STAGEB, mBase, nQ0 + (qn >> 3) * 128, qn & 7);
            asm volatile("cp.async.wait_group 1;" ::: "memory");
        } else {
            asm volatile("cp.async.wait_group 0;" ::: "memory");
        }
        __syncthreads();

        if (kc == 0) {
            #pragma unroll
            for (int mf = 0; mf < 2; mf++)
                #pragma unroll
                for (int nf = 0; nf < 8; nf++)
                    #pragma unroll
                    for (int r = 0; r < 4; r++) c[mf][nf][r] = 0.f;
        }

        const uint32_t sbuf = sb + (qc & 1) * STAGEB;
        #pragma unroll
        for (int k16 = 0; k16 < 2; k16++) {
            const uint32_t kb = k16 * 32;
            uint32_t a0[2][4], a1[2][4];
            #pragma unroll
            for (int mf = 0; mf < 2; mf++) {
                ldsm4(a0[mf][0], a0[mf][1], a0[mf][2], a0[mf][3],
                      sbuf + aLane + mf * (16 * SLDA) + kb);
                ldsm4(a1[mf][0], a1[mf][1], a1[mf][2], a1[mf][3],
                      sbuf + SUBT + aLane + mf * (16 * SLDA) + kb);
            }
            #pragma unroll
            for (int np = 0; np < 2; np++) {
                const int n0 = 2 * np;
                uint32_t P[2][4], Q[2][4];
                #pragma unroll
                for (int j = 0; j < 2; j++) {
                    ldsm4(P[j][0], P[j][1], P[j][2], P[j][3],
                          sbuf + 2 * SUBT + bLane + (n0 + j) * (16 * SLDA) + kb);
                    ldsm4(Q[j][0], Q[j][1], Q[j][2], Q[j][3],
                          sbuf + 3 * SUBT + bLane + (n0 + j) * (16 * SLDA) + kb);
                }
                #pragma unroll
                for (int j = 0; j < 2; j++)
                    #pragma unroll
                    for (int mf = 0; mf < 2; mf++) {
                        mma16816(c[mf][2*(n0+j)],   a0[mf], P[j][0], P[j][1]);
                        mma16816(c[mf][2*(n0+j)+1], a0[mf], P[j][2], P[j][3]);
                    }
                #pragma unroll
                for (int j = 0; j < 2; j++)
                    #pragma unroll
                    for (int mf = 0; mf < 2; mf++) {
                        mma16816(c[mf][2*(n0+j)],   a1[mf], P[j][0], P[j][1]);
                        mma16816(c[mf][2*(n0+j)+1], a1[mf], P[j][2], P[j][3]);
                    }
                #pragma unroll
                for (int j = 0; j < 2; j++)
                    #pragma unroll
                    for (int mf = 0; mf < 2; mf++) {
                        mma16816(c[mf][2*(n0+j)],   a0[mf], Q[j][0], Q[j][1]);
                        mma16816(c[mf][2*(n0+j)+1], a0[mf], Q[j][2], Q[j][3]);
                    }
            }
        }
        __syncthreads();

        if (kc == NCHUNK - 1) {
            const int colBase = nQ0 + nt * 128 + wn * 64 + (lane & 3) * 2;
            float En16[16];
            #pragma unroll
            for (int nf = 0; nf < 8; nf++) {
                En16[nf*2]   = __ldg(&g_enorm[colBase + nf * 8]);
                En16[nf*2+1] = __ldg(&g_enorm[colBase + nf * 8 + 1]);
            }
            #pragma unroll
            for (int mf = 0; mf < 2; mf++)
                #pragma unroll
                for (int rh = 0; rh < 2; rh++) {
                    float s[16];
                    #pragma unroll
                    for (int nf = 0; nf < 8; nf++) {
                        s[nf*2]   = En16[nf*2]   - 0.0078125f * c[mf][nf][rh*2];
                        s[nf*2+1] = En16[nf*2+1] - 0.0078125f * c[mf][nf][rh*2+1];
                    }
                    float m = s[0];
                    #pragma unroll
                    for (int i = 1; i < 16; i++) m = fminf(m, s[i]);
                    int col = colBase;
                    #pragma unroll
                    for (int i = 15; i >= 0; i--)
                        if (s[i] == m) col = colBase + (i >> 1) * 8 + (i & 1);
                    unsigned long long key =
                        ((unsigned long long)fkey(m) << 32) | (unsigned)col;
                    int slot = mf * 2 + rh;
                    best4[slot] = umin64(best4[slot], key);
                }
        }
    }

    // quad reduction, smem combine, global atomicMin
    #pragma unroll
    for (int s = 0; s < 4; s++) {
        best4[s] = umin64(best4[s], __shfl_xor_sync(0xffffffffu, best4[s], 1));
        best4[s] = umin64(best4[s], __shfl_xor_sync(0xffffffffu, best4[s], 2));
    }
    if ((lane & 3) == 0 && wn == 0) {
        #pragma unroll
        for (int s = 0; s < 4; s++) {
            int row = wm * 32 + (s >> 1) * 16 + (s & 1) * 8 + (lane >> 2);
            sbest[row] = best4[s];
        }
    }
    __syncthreads();
    if ((lane & 3) == 0 && wn == 1) {
        #pragma unroll
        for (int s = 0; s < 4; s++) {
            int row = wm * 32 + (s >> 1) * 16 + (s & 1) * 8 + (lane >> 2);
            atomicMin(&g_best[mBase + row], umin64(sbest[row], best4[s]));
        }
    }
}

// ---------------- gather z_q, loss, segment sums (4 rows / 256-thread block) ----------------
__global__ void gather_kernel(const float* __restrict__ z, const float* __restrict__ embed,
                              float* __restrict__ out_zq, float* __restrict__ out_idx) {
    const int sub = threadIdx.x >> 6;        // row within block (0..3)
    const int d4  = threadIdx.x & 63;        // 64 threads x 4 dims
    const int t = blockIdx.x * 4 + sub;
    unsigned long long best = g_best[t];
    int idx = (int)(unsigned)(best & 0xFFFFFFFFull);
    float4 zq = *reinterpret_cast<const float4*>(embed + (size_t)idx * DQ + d4 * 4);
    float4 zv = *reinterpret_cast<const float4*>(z + (size_t)t * DQ + d4 * 4);
    *reinterpret_cast<float4*>(out_zq + (size_t)t * DQ + d4 * 4) = zq;
    float* es = g_es + (size_t)idx * DQ + d4 * 4;
    red2(es,     zv.x, zv.y);
    red2(es + 2, zv.z, zv.w);
    float dx = zq.x - zv.x, dy = zq.y - zv.y, dz = zq.z - zv.z, dw = zq.w - zv.w;
    float s = dx*dx + dy*dy + dz*dz + dw*dw;
    #pragma unroll
    for (int off = 16; off; off >>= 1) s += __shfl_down_sync(0xffffffffu, s, off);
    __shared__ float sh[8];
    if ((threadIdx.x & 31) == 0) sh[threadIdx.x >> 5] = s;
    if (d4 == 0) {
        out_idx[t] = (float)idx;
        atomicAdd(&g_cs[idx], 1.0f);
    }
    __syncthreads();
    if (threadIdx.x == 0) {
        float tot = 0.f;
        #pragma unroll
        for (int w = 0; w < 8; w++) tot += sh[w];
        atomicAdd(&g_loss, (double)tot);
    }
}

// ---------------- EMA cluster size + total + loss write ----------------
__global__ void ncs_kernel(const float* __restrict__ cluster_size,
                           float* __restrict__ out_ncs, float* __restrict__ out_loss) {
    int k = blockIdx.x * blockDim.x + threadIdx.x;   // 4096
    float ncs = cluster_size[k] * DECAYF + ONEMDECAYF * g_cs[k];
    out_ncs[k] = ncs;
    float s = ncs;
    #pragma unroll
    for (int off = 16; off; off >>= 1) s += __shfl_down_sync(0xffffffffu, s, off);
    __shared__ float sh[8];
    int lt = threadIdx.x;
    if ((lt & 31) == 0) sh[lt >> 5] = s;
    __syncthreads();
    if (lt == 0) {
        float tot = 0.f;
        #pragma unroll
        for (int w = 0; w < 8; w++) tot += sh[w];
        atomicAdd(&g_tot, tot);
    }
    if (k == 0) out_loss[0] = (float)(2.0 * g_loss / (double)((size_t)MQ * DQ));
}

// ---------------- EMA embed_avg + normalized embed ----------------
__global__ void final_kernel(const float* __restrict__ embed_avg,
                             const float* __restrict__ out_ncs,
                             float* __restrict__ out_new_embed,
                             float* __restrict__ out_nea) {
    int i = blockIdx.x * blockDim.x + threadIdx.x;   // K*D
    int k = i >> 8;
    float tot = g_tot;
    float ncs = out_ncs[k];
    float csn = (ncs + EPSF) / (tot + (float)KQ * EPSF) * tot;
    float nea = embed_avg[i] * DECAYF + ONEMDECAYF * g_es[i];
    out_nea[i] = nea;
    out_new_embed[i] = nea / csn;
}

// ---------------- launch ----------------
extern "C" void kernel_launch(void* const* d_in, const int* in_sizes, int n_in,
                              void* d_out, int out_size) {
    const float* z            = (const float*)d_in[0];
    const float* embed        = (const float*)d_in[1];
    const float* cluster_size = (const float*)d_in[2];
    const float* embed_avg    = (const float*)d_in[3];

    float* out          = (float*)d_out;
    float* out_zq       = out;                                   // [B,N,D]
    float* out_idx      = out + (size_t)MQ * DQ;                 // [B,N]
    float* out_loss     = out_idx + MQ;                          // [1]
    float* out_newembed = out_loss + 1;                          // [K,D]
    float* out_ncs      = out_newembed + (size_t)KQ * DQ;        // [K]
    float* out_nea      = out_ncs + KQ;                          // [K,D]

    cudaFuncSetAttribute(dist_hmma_kernel,
                         cudaFuncAttributeMaxDynamicSharedMemorySize, SMEM_DIST);

    split_z_kernel<<<ZBLKS + 256, 256>>>(z);
    split_e_kernel<<<EBLKS + 1041, 256>>>(embed);
    enorm_kernel<<<KQ, 64>>>(embed);
    dist_hmma_kernel<<<(MQ / 128) * 4, 256, SMEM_DIST>>>();
    gather_kernel<<<MQ / 4, 256>>>(z, embed, out_zq, out_idx);
    ncs_kernel<<<KQ / 256, 256>>>(cluster_size, out_ncs, out_loss);
    final_kernel<<<(KQ * DQ) / 256, 256>>>(embed_avg, out_ncs, out_newembed, out_nea);
}

// round 15
// speedup vs baseline: 1.0884x; 1.0154x over previous
#include <cuda_runtime.h>
#include <cuda_fp16.h>
#include <cstdint>

// Problem constants
#define BQ 16
#define NQ 4096
#define DQ 256
#define KQ 4096
#define MQ (BQ*NQ)   // 65536 tokens

#define DECAYF 0.99f
#define ONEMDECAYF 0.01f
#define EPSF 1e-5f

// fp16 2-way split, shared-fragment 3-product scheme
#define ROWH 512             // halfs per row
#define ROWB 1024            // bytes per row
#define SLDA 80              // smem sub-tile row stride (bytes), conflict-free
#define SUBT (128*SLDA)      // 10240 bytes per 128x32half sub-tile
#define STAGEB (4*SUBT)      // Ah0|Ah1|Bg0|Bg1 = 40960
#define NCHUNK 8             // k32 chunks covering D=256
#define NQUARTER 1024        // codes per CTA (N-split x4)
#define NTILES (NQUARTER/128) // 8
#define TOTQ (NTILES*NCHUNK) // 64
#define SMEM_DIST (2*STAGEB + 1024 + 4096)   // 2 stages + sbest + sEn = 87040

// ---------------- device scratch (no allocations allowed) ----------------
__device__ __align__(16) __half g_zbig[(size_t)MQ * ROWH];   // [M][h0|h1] (z*16)
__device__ __align__(16) __half g_ebig[(size_t)KQ * ROWH];   // [K][g0|g1] (e*16)
__device__ unsigned long long g_best[MQ];   // (ordered score <<32)|index
__device__ float  g_enorm[KQ];
__device__ float  g_cs[KQ];
__device__ float  g_es[KQ*DQ];
__device__ double g_loss;
__device__ float  g_tot;

// ---------------- helpers ----------------
__device__ __forceinline__ uint32_t s2u(const void* p) {
    uint32_t a;
    asm("{ .reg .u64 t; cvta.to.shared.u64 t, %1; cvt.u32.u64 %0, t; }"
        : "=r"(a) : "l"(p));
    return a;
}
__device__ __forceinline__ unsigned int fkey(float f) {
    unsigned int b = __float_as_uint(f);
    return b ^ ((b & 0x80000000u) ? 0xFFFFFFFFu : 0x80000000u);
}
__device__ __forceinline__ unsigned long long umin64(unsigned long long a,
                                                     unsigned long long b) {
    return a < b ? a : b;
}
__device__ __forceinline__ void cp16(uint32_t dst, const void* src) {
    asm volatile("cp.async.cg.shared.global [%0], [%1], 16;" :: "r"(dst), "l"(src));
}
#define CP_COMMIT() asm volatile("cp.async.commit_group;" ::: "memory")

__device__ __forceinline__ void ldsm4(uint32_t& r0, uint32_t& r1, uint32_t& r2,
                                      uint32_t& r3, uint32_t a) {
    asm volatile("ldmatrix.sync.aligned.m8n8.x4.shared.b16 {%0,%1,%2,%3}, [%4];"
                 : "=r"(r0), "=r"(r1), "=r"(r2), "=r"(r3) : "r"(a));
}
__device__ __forceinline__ void mma16816(float* c, const uint32_t* a,
                                         uint32_t b0, uint32_t b1) {
    asm volatile(
        "mma.sync.aligned.m16n8k16.row.col.f32.f16.f16.f32 "
        "{%0,%1,%2,%3}, {%4,%5,%6,%7}, {%8,%9}, {%0,%1,%2,%3};"
        : "+f"(c[0]), "+f"(c[1]), "+f"(c[2]), "+f"(c[3])
        : "r"(a[0]), "r"(a[1]), "r"(a[2]), "r"(a[3]), "r"(b0), "r"(b1));
}
__device__ __forceinline__ void red4(float* addr, float a, float b, float c, float d) {
    asm volatile("red.global.add.v4.f32 [%0], {%1, %2, %3, %4};"
                 :: "l"(addr), "f"(a), "f"(b), "f"(c), "f"(d) : "memory");
}

// ---------------- splits (scale x16, fp16 2-way Dekker) + g_best init ----------------
#define ZBLKS (MQ*DQ/2/256)   // 32768
__global__ void split_z_kernel(const float* __restrict__ z) {
    int b = blockIdx.x;
    if (b >= ZBLKS) {
        int i = (b - ZBLKS) * 256 + threadIdx.x;   // 256 blocks x 256 = 65536
        g_best[i] = 0xFFFFFFFFFFFFFFFFull;
        return;
    }
    int i = b * 256 + threadIdx.x;
    int idx = i * 2;
    int row = idx >> 8;
    int d = idx & 255;
    float2 v = *reinterpret_cast<const float2*>(z + idx);
    float sx = v.x * 16.0f, sy = v.y * 16.0f;
    __half hx0 = __float2half(sx), hy0 = __float2half(sy);
    __half hx1 = __float2half(sx - __half2float(hx0));
    __half hy1 = __float2half(sy - __half2float(hy0));
    __half* base = g_zbig + (size_t)row * ROWH + d;
    __half2 p0; p0.x = hx0; p0.y = hy0;
    __half2 p1; p1.x = hx1; p1.y = hy1;
    *reinterpret_cast<__half2*>(base)       = p0;   // h0
    *reinterpret_cast<__half2*>(base + 256) = p1;   // h1
}

#define EBLKS (KQ*DQ/2/256)   // 2048
__global__ void split_e_kernel(const float* __restrict__ e) {
    int b = blockIdx.x;
    if (b >= EBLKS) {
        int tb = b - EBLKS;
        if (tb < 1024) {                      // zero g_es (1M floats via float4)
            int i = tb * 256 + threadIdx.x;
            reinterpret_cast<float4*>(g_es)[i] = make_float4(0.f, 0.f, 0.f, 0.f);
        } else {                              // zero g_cs + scalars
            int t = threadIdx.x;
            int k0 = (tb - 1024) * 256 + t;
            if (k0 < KQ) g_cs[k0] = 0.f;
            if (tb == 1024 && t == 0) { g_loss = 0.0; g_tot = 0.f; }
        }
        return;
    }
    int i = b * 256 + threadIdx.x;
    int idx = i * 2;
    int row = idx >> 8;
    int d = idx & 255;
    float2 v = *reinterpret_cast<const float2*>(e + idx);
    float sx = v.x * 16.0f, sy = v.y * 16.0f;
    __half gx0 = __float2half(sx), gy0 = __float2half(sy);
    __half gx1 = __float2half(sx - __half2float(gx0));
    __half gy1 = __float2half(sy - __half2float(gy0));
    __half* base = g_ebig + (size_t)row * ROWH + d;
    __half2 p0; p0.x = gx0; p0.y = gy0;
    __half2 p1; p1.x = gx1; p1.y = gy1;
    *reinterpret_cast<__half2*>(base)       = p0;   // g0
    *reinterpret_cast<__half2*>(base + 256) = p1;   // g1
}

// ---------------- ||e_k||^2 (unscaled fp32) ----------------
__global__ void enorm_kernel(const float* __restrict__ embed) {
    int k = blockIdx.x;
    int t = threadIdx.x;                 // 64 threads x 4 floats
    const float4* row = reinterpret_cast<const float4*>(embed + (size_t)k * DQ);
    float4 v = row[t];
    float s = v.x*v.x + v.y*v.y + v.z*v.z + v.w*v.w;
    #pragma unroll
    for (int off = 16; off; off >>= 1) s += __shfl_down_sync(0xffffffffu, s, off);
    __shared__ float sh[2];
    if ((t & 31) == 0) sh[t >> 5] = s;
    __syncthreads();
    if (t == 0) g_enorm[k] = sh[0] + sh[1];
}

// ---------------- chunk loader: Ah0|Ah1|Bg0|Bg1 sub-tiles ----------------
__device__ __forceinline__ void issue_chunk(uint32_t stage, int mBase, int nBase, int kc) {
    const char* zB = (const char*)g_zbig;
    const char* eB = (const char*)g_ebig;
    const int kb = kc * 64;
    #pragma unroll
    for (int j = 0; j < 8; j++) {
        int id = threadIdx.x + j * 256;     // 0..2047
        int sub = id >> 9;
        int r = (id >> 2) & 127;
        int c = (id & 3) * 16;
        const char* src = (sub < 2)
            ? zB + (size_t)(mBase + r) * ROWB + sub * 512 + kb + c
            : eB + (size_t)(nBase + r) * ROWB + (sub - 2) * 512 + kb + c;
        cp16(stage + sub * SUBT + r * SLDA + c, src);
    }
    CP_COMMIT();
}

// ---------------- fused HMMA distance GEMM + argmin ----------------
__global__ __launch_bounds__(256, 2)
void dist_hmma_kernel() {
    extern __shared__ char smem[];
    uint32_t sb = s2u(smem);
    const int tid = threadIdx.x;
    const int lane = tid & 31;
    const int wid = tid >> 5;
    const int wm = wid & 3;
    const int wn = wid >> 2;
    const int mBase = (int)(blockIdx.x >> 2) * 128;
    const int nQ0   = (int)(blockIdx.x & 3) * NQUARTER;

    unsigned long long* sbest = (unsigned long long*)(smem + 2 * STAGEB);
    float* sEn = (float*)(smem + 2 * STAGEB + 1024);

    const uint32_t aLane = (uint32_t)((wm * 32 + (lane & 15)) * SLDA + ((lane & 16) ? 16 : 0));
    const uint32_t bLane = (uint32_t)((wn * 64 + ((lane >> 4) & 1) * 8 + (lane & 7)) * SLDA
                                      + ((lane & 8) ? 16 : 0));

    unsigned long long best4[4];
    #pragma unroll
    for (int s = 0; s < 4; s++) best4[s] = 0xFFFFFFFFFFFFFFFFull;

    float c[2][8][4];

    // prologue: stage this CTA's enorm slice (1024 floats) + chunk 0.
    // The En cp.asyncs join chunk 0's commit group.
    cp16(sb + 2 * STAGEB + 1024 + tid * 16, (const char*)(g_enorm + nQ0) + tid * 16);
    issue_chunk(sb, mBase, nQ0, 0);

    for (int qc = 0; qc < TOTQ; qc++) {
        const int nt = qc >> 3;
        const int kc = qc & 7;
        if (qc < TOTQ - 1) {
            const int qn = qc + 1;
            issue_chunk(sb + (qn & 1) * STAGEB, mBase, nQ0 + (qn >> 3) * 128, qn & 7);
            asm volatile("cp.async.wait_group 1;" ::: "memory");
        } else {
            asm volatile("cp.async.wait_group 0;" ::: "memory");
        }
        __syncthreads();

        if (kc == 0) {
            #pragma unroll
            for (int mf = 0; mf < 2; mf++)
                #pragma unroll
                for (int nf = 0; nf < 8; nf++)
                    #pragma unroll
                    for (int r = 0; r < 4; r++) c[mf][nf][r] = 0.f;
        }

        const uint32_t sbuf = sb + (qc & 1) * STAGEB;
        #pragma unroll
        for (int k16 = 0; k16 < 2; k16++) {
            const uint32_t kb = k16 * 32;
            uint32_t a0[2][4], a1[2][4];
            #pragma unroll
            for (int mf = 0; mf < 2; mf++) {
                ldsm4(a0[mf][0], a0[mf][1], a0[mf][2], a0[mf][3],
                      sbuf + aLane + mf * (16 * SLDA) + kb);
                ldsm4(a1[mf][0], a1[mf][1], a1[mf][2], a1[mf][3],
                      sbuf + SUBT + aLane + mf * (16 * SLDA) + kb);
            }
            #pragma unroll
            for (int np = 0; np < 2; np++) {
                const int n0 = 2 * np;
                uint32_t P[2][4], Q[2][4];
                #pragma unroll
                for (int j = 0; j < 2; j++) {
                    ldsm4(P[j][0], P[j][1], P[j][2], P[j][3],
                          sbuf + 2 * SUBT + bLane + (n0 + j) * (16 * SLDA) + kb);
                    ldsm4(Q[j][0], Q[j][1], Q[j][2], Q[j][3],
                          sbuf + 3 * SUBT + bLane + (n0 + j) * (16 * SLDA) + kb);
                }
                #pragma unroll
                for (int j = 0; j < 2; j++)
                    #pragma unroll
                    for (int mf = 0; mf < 2; mf++) {
                        mma16816(c[mf][2*(n0+j)],   a0[mf], P[j][0], P[j][1]);
                        mma16816(c[mf][2*(n0+j)+1], a0[mf], P[j][2], P[j][3]);
                    }
                #pragma unroll
                for (int j = 0; j < 2; j++)
                    #pragma unroll
                    for (int mf = 0; mf < 2; mf++) {
                        mma16816(c[mf][2*(n0+j)],   a1[mf], P[j][0], P[j][1]);
                        mma16816(c[mf][2*(n0+j)+1], a1[mf], P[j][2], P[j][3]);
                    }
                #pragma unroll
                for (int j = 0; j < 2; j++)
                    #pragma unroll
                    for (int mf = 0; mf < 2; mf++) {
                        mma16816(c[mf][2*(n0+j)],   a0[mf], Q[j][0], Q[j][1]);
                        mma16816(c[mf][2*(n0+j)+1], a0[mf], Q[j][2], Q[j][3]);
                    }
            }
        }
        __syncthreads();

        if (kc == NCHUNK - 1) {
            // epilogue for this N-tile: scores + running argmin (En from smem)
            const int lcolBase = nt * 128 + wn * 64 + (lane & 3) * 2;
            const int colBase = nQ0 + lcolBase;
            float En16[16];
            #pragma unroll
            for (int nf = 0; nf < 8; nf++) {
                En16[nf*2]   = sEn[lcolBase + nf * 8];
                En16[nf*2+1] = sEn[lcolBase + nf * 8 + 1];
            }
            #pragma unroll
            for (int mf = 0; mf < 2; mf++)
                #pragma unroll
                for (int rh = 0; rh < 2; rh++) {
                    float s[16];
                    #pragma unroll
                    for (int nf = 0; nf < 8; nf++) {
                        s[nf*2]   = En16[nf*2]   - 0.0078125f * c[mf][nf][rh*2];
                        s[nf*2+1] = En16[nf*2+1] - 0.0078125f * c[mf][nf][rh*2+1];
                    }
                    float m = s[0];
                    #pragma unroll
                    for (int i = 1; i < 16; i++) m = fminf(m, s[i]);
                    int col = colBase;
                    #pragma unroll
                    for (int i = 15; i >= 0; i--)
                        if (s[i] == m) col = colBase + (i >> 1) * 8 + (i & 1);
                    unsigned long long key =
                        ((unsigned long long)fkey(m) << 32) | (unsigned)col;
                    int slot = mf * 2 + rh;
                    best4[slot] = umin64(best4[slot], key);
                }
        }
    }

    // quad reduction, smem combine, global atomicMin
    #pragma unroll
    for (int s = 0; s < 4; s++) {
        best4[s] = umin64(best4[s], __shfl_xor_sync(0xffffffffu, best4[s], 1));
        best4[s] = umin64(best4[s], __shfl_xor_sync(0xffffffffu, best4[s], 2));
    }
    if ((lane & 3) == 0 && wn == 0) {
        #pragma unroll
        for (int s = 0; s < 4; s++) {
            int row = wm * 32 + (s >> 1) * 16 + (s & 1) * 8 + (lane >> 2);
            sbest[row] = best4[s];
        }
    }
    __syncthreads();
    if ((lane & 3) == 0 && wn == 1) {
        #pragma unroll
        for (int s = 0; s < 4; s++) {
            int row = wm * 32 + (s >> 1) * 16 + (s & 1) * 8 + (lane >> 2);
            atomicMin(&g_best[mBase + row], umin64(sbest[row], best4[s]));
        }
    }
}

// ---------------- gather z_q, loss, segment sums (4 rows / 256-thread block) ----------------
__global__ void gather_kernel(const float* __restrict__ z, const float* __restrict__ embed,
                              float* __restrict__ out_zq, float* __restrict__ out_idx) {
    const int sub = threadIdx.x >> 6;        // row within block (0..3)
    const int d4  = threadIdx.x & 63;        // 64 threads x 4 dims
    const int t = blockIdx.x * 4 + sub;
    unsigned long long best = g_best[t];
    int idx = (int)(unsigned)(best & 0xFFFFFFFFull);
    float4 zq = *reinterpret_cast<const float4*>(embed + (size_t)idx * DQ + d4 * 4);
    float4 zv = *reinterpret_cast<const float4*>(z + (size_t)t * DQ + d4 * 4);
    *reinterpret_cast<float4*>(out_zq + (size_t)t * DQ + d4 * 4) = zq;
    red4(g_es + (size_t)idx * DQ + d4 * 4, zv.x, zv.y, zv.z, zv.w);
    float dx = zq.x - zv.x, dy = zq.y - zv.y, dz = zq.z - zv.z, dw = zq.w - zv.w;
    float s = dx*dx + dy*dy + dz*dz + dw*dw;
    #pragma unroll
    for (int off = 16; off; off >>= 1) s += __shfl_down_sync(0xffffffffu, s, off);
    __shared__ float sh[8];
    if ((threadIdx.x & 31) == 0) sh[threadIdx.x >> 5] = s;
    if (d4 == 0) {
        out_idx[t] = (float)idx;
        atomicAdd(&g_cs[idx], 1.0f);
    }
    __syncthreads();
    if (threadIdx.x == 0) {
        float tot = 0.f;
        #pragma unroll
        for (int w = 0; w < 8; w++) tot += sh[w];
        atomicAdd(&g_loss, (double)tot);
    }
}

// ---------------- EMA cluster size + total + loss write ----------------
__global__ void ncs_kernel(const float* __restrict__ cluster_size,
                           float* __restrict__ out_ncs, float* __restrict__ out_loss) {
    int k = blockIdx.x * blockDim.x + threadIdx.x;   // 4096
    float ncs = cluster_size[k] * DECAYF + ONEMDECAYF * g_cs[k];
    out_ncs[k] = ncs;
    float s = ncs;
    #pragma unroll
    for (int off = 16; off; off >>= 1) s += __shfl_down_sync(0xffffffffu, s, off);
    __shared__ float sh[8];
    int lt = threadIdx.x;
    if ((lt & 31) == 0) sh[lt >> 5] = s;
    __syncthreads();
    if (lt == 0) {
        float tot = 0.f;
        #pragma unroll
        for (int w = 0; w < 8; w++) tot += sh[w];
        atomicAdd(&g_tot, tot);
    }
    if (k == 0) out_loss[0] = (float)(2.0 * g_loss / (double)((size_t)MQ * DQ));
}

// ---------------- EMA embed_avg + normalized embed ----------------
__global__ void final_kernel(const float* __restrict__ embed_avg,
                             const float* __restrict__ out_ncs,
                             float* __restrict__ out_new_embed,
                             float* __restrict__ out_nea) {
    int i = blockIdx.x * blockDim.x + threadIdx.x;   // K*D
    int k = i >> 8;
    float tot = g_tot;
    float ncs = out_ncs[k];
    float csn = (ncs + EPSF) / (tot + (float)KQ * EPSF) * tot;
    float nea = embed_avg[i] * DECAYF + ONEMDECAYF * g_es[i];
    out_nea[i] = nea;
    out_new_embed[i] = nea / csn;
}

// ---------------- launch ----------------
extern "C" void kernel_launch(void* const* d_in, const int* in_sizes, int n_in,
                              void* d_out, int out_size) {
    const float* z            = (const float*)d_in[0];
    const float* embed        = (const float*)d_in[1];
    const float* cluster_size = (const float*)d_in[2];
    const float* embed_avg    = (const float*)d_in[3];

    float* out          = (float*)d_out;
    float* out_zq       = out;                                   // [B,N,D]
    float* out_idx      = out + (size_t)MQ * DQ;                 // [B,N]
    float* out_loss     = out_idx + MQ;                          // [1]
    float* out_newembed = out_loss + 1;                          // [K,D]
    float* out_ncs      = out_newembed + (size_t)KQ * DQ;        // [K]
    float* out_nea      = out_ncs + KQ;                          // [K,D]

    cudaFuncSetAttribute(dist_hmma_kernel,
                         cudaFuncAttributeMaxDynamicSharedMemorySize, SMEM_DIST);

    split_z_kernel<<<ZBLKS + 256, 256>>>(z);
    split_e_kernel<<<EBLKS + 1041, 256>>>(embed);
    enorm_kernel<<<KQ, 64>>>(embed);
    dist_hmma_kernel<<<(MQ / 128) * 4, 256, SMEM_DIST>>>();
    gather_kernel<<<MQ / 4, 256>>>(z, embed, out_zq, out_idx);
    ncs_kernel<<<KQ / 256, 256>>>(cluster_size, out_ncs, out_loss);
    final_kernel<<<(KQ * DQ) / 256, 256>>>(embed_avg, out_ncs, out_newembed, out_nea);
}